// round 16
// baseline (speedup 1.0000x reference)
#include <cuda_runtime.h>
#include <cuda_bf16.h>
#include <cuda_fp16.h>
#include <cstdint>

#define B_   32
#define D_   128
#define LC_  2048
#define LQ_  512

typedef unsigned int u32;

// ---------------- scratch planes ----------------
__device__ u32 g_E[(size_t)B_ * LC_ * LQ_ / 2];        // E'' fp16 single plane
__device__ u32 g_Cwhi[(size_t)B_ * D_ * LC_ / 2];      // C*w_mul bf16 2L (k_S)
__device__ u32 g_Cwlo[(size_t)B_ * D_ * LC_ / 2];
__device__ u32 g_Cfhi[(size_t)B_ * D_ * LC_ / 2];      // C' = C*cmask*16*exp(s0), fp16 2L (k_T)
__device__ u32 g_Cflo[(size_t)B_ * D_ * LC_ / 2];
__device__ u32 g_Qhi[(size_t)B_ * D_ * LQ_ / 2];       // Q bf16 2L (k_S)
__device__ u32 g_Qlo[(size_t)B_ * D_ * LQ_ / 2];
__device__ u32 g_Qfhi[(size_t)B_ * D_ * LQ_ / 2];      // Q fp16 2L (k_AB)
__device__ u32 g_Qflo[(size_t)B_ * D_ * LQ_ / 2];
__device__ u32 g_T[(size_t)B_ * LQ_ * D_ / 2];         // T fp16 single plane
__device__ float g_s0[B_ * LC_];
__device__ float g_s1[B_ * LQ_];
__device__ float g_Z1p[B_ * LC_ * 4];
__device__ float g_Z2p[B_ * LQ_ * 16];

// ---------------- helpers ----------------
__device__ __forceinline__ u32 s2u(const void* p) {
    u32 a; asm("{ .reg .u64 t; cvta.to.shared.u64 t, %1; cvt.u32.u64 %0, t; }" : "=r"(a) : "l"(p));
    return a;
}
#define SWZ(x) ((u32)(x) ^ ((((u32)(x)) >> 3) & 0x70))

__device__ __forceinline__ void cpa16(u32 dst, const void* src) {
    asm volatile("cp.async.cg.shared.global [%0], [%1], 16;" :: "r"(dst), "l"(src));
}
#define CP_COMMIT() asm volatile("cp.async.commit_group;")
#define CP_WAIT0()  asm volatile("cp.async.wait_group 0;")
#define CP_WAIT1()  asm volatile("cp.async.wait_group 1;")

__device__ __forceinline__ void splt(float v, u32 &hi, u32 &lo) {     // bf16 2-limb
    __nv_bfloat16 h = __float2bfloat16(v);
    __nv_bfloat16 l = __float2bfloat16(v - __bfloat162float(h));
    hi = (u32)__bfloat16_as_ushort(h);
    lo = (u32)__bfloat16_as_ushort(l);
}
__device__ __forceinline__ void splt16(float v, u32 &hi, u32 &lo) {   // fp16 2-limb
    __half h = __float2half(v);
    __half l = __float2half(v - __half2float(h));
    hi = (u32)__half_as_ushort(h);
    lo = (u32)__half_as_ushort(l);
}

// fast exp(v)/16 on the FMA pipe: 2^(v*log2e - 4), magic-add split + deg-5 poly
__device__ __forceinline__ float fexp16(float v) {
    float y = v * 1.4426950408889634f;
    float t = y + 12582912.f;                       // 2^23 + 2^22 magic
    int n = __float_as_int(t) - 0x4B400000 - 4;     // round(y) - 4  (/16 folded)
    float f = y - (t - 12582912.f);                 // f in [-0.5, 0.5]
    float p = 0.0013333558f;
    p = fmaf(p, f, 0.0096181291f);
    p = fmaf(p, f, 0.0555041087f);
    p = fmaf(p, f, 0.2402265069f);
    p = fmaf(p, f, 0.6931471806f);
    p = fmaf(p, f, 1.0f);
    return __int_as_float(__float_as_int(p) + (n << 23));
}

__device__ __forceinline__ void ldsm4(u32 addr, u32 r[4]) {
    asm volatile("ldmatrix.sync.aligned.m8n8.x4.shared.b16 {%0,%1,%2,%3}, [%4];"
                 : "=r"(r[0]), "=r"(r[1]), "=r"(r[2]), "=r"(r[3]) : "r"(addr));
}
__device__ __forceinline__ void ldsm4t(u32 addr, u32 r[4]) {
    asm volatile("ldmatrix.sync.aligned.m8n8.x4.trans.shared.b16 {%0,%1,%2,%3}, [%4];"
                 : "=r"(r[0]), "=r"(r[1]), "=r"(r[2]), "=r"(r[3]) : "r"(addr));
}
template<int F16>
__device__ __forceinline__ void mmaop(float d[4], const u32 a[4], u32 b0, u32 b1) {
    if (F16)
        asm volatile("mma.sync.aligned.m16n8k16.row.col.f32.f16.f16.f32 "
                     "{%0,%1,%2,%3}, {%4,%5,%6,%7}, {%8,%9}, {%0,%1,%2,%3};"
                     : "+f"(d[0]), "+f"(d[1]), "+f"(d[2]), "+f"(d[3])
                     : "r"(a[0]), "r"(a[1]), "r"(a[2]), "r"(a[3]), "r"(b0), "r"(b1));
    else
        asm volatile("mma.sync.aligned.m16n8k16.row.col.f32.bf16.bf16.f32 "
                     "{%0,%1,%2,%3}, {%4,%5,%6,%7}, {%8,%9}, {%0,%1,%2,%3};"
                     : "+f"(d[0]), "+f"(d[1]), "+f"(d[2]), "+f"(d[3])
                     : "r"(a[0]), "r"(a[1]), "r"(a[2]), "r"(a[3]), "r"(b0), "r"(b1));
}
__device__ __forceinline__ uint4 lds128(u32 a) {
    uint4 v;
    asm volatile("ld.shared.v4.b32 {%0,%1,%2,%3}, [%4];"
                 : "=r"(v.x), "=r"(v.y), "=r"(v.z), "=r"(v.w) : "r"(a));
    return v;
}
__device__ __forceinline__ void sts32(u32 a, u32 v) { asm volatile("st.shared.b32 [%0], %1;" :: "r"(a), "r"(v)); }

// ---------------- chunk copies (L = limb count) ----------------
template<int NT, int L, typename H>
__device__ __forceinline__ void cpyT64(u32 dstBase, const H* srcHi, const H* srcLo,
                                       size_t rowStride, int tid) {
    #pragma unroll
    for (int t = 0; t < (1024 * L) / NT; t++) {
        int u = tid + t * NT;
        int limb = u >> 10, rem = u & 1023;
        int row = rem >> 4, ucol = rem & 15;
        const H* src = (limb ? srcLo : srcHi) + (size_t)row * rowStride + ucol * 8;
        u32 dst = dstBase + limb * 16384 + (ucol >> 3) * 8192 + SWZ(row * 128 + (ucol & 7) * 16);
        cpa16(dst, src);
    }
}
template<int NT, int L, typename H>
__device__ __forceinline__ void cpyT32(u32 dstBase, const H* srcHi, const H* srcLo,
                                       size_t rowStride, int tid) {
    #pragma unroll
    for (int t = 0; t < (512 * L) / NT; t++) {
        int u = tid + t * NT;
        int limb = u >> 9, rem = u & 511;
        int row = rem >> 4, ucol = rem & 15;
        const H* src = (limb ? srcLo : srcHi) + (size_t)row * rowStride + ucol * 8;
        u32 dst = dstBase + limb * 8192 + (ucol >> 3) * 4096 + SWZ(row * 128 + (ucol & 7) * 16);
        cpa16(dst, src);
    }
}
template<int NT, int L, typename H>
__device__ __forceinline__ void cpyN128(u32 dstBase, const H* srcHi, const H* srcLo,
                                        size_t rowStride, int tid) {
    #pragma unroll
    for (int t = 0; t < (1024 * L) / NT; t++) {
        int u = tid + t * NT;
        int limb = u >> 10, rem = u & 1023;
        int row = rem >> 3, ucol = rem & 7;
        const H* src = (limb ? srcLo : srcHi) + (size_t)row * rowStride + ucol * 8;
        u32 dst = dstBase + limb * 16384 + SWZ(row * 128 + ucol * 16);
        cpa16(dst, src);
    }
}

// ---------------- warp MMA over one chunk ----------------------------------
template<int MI, int AT, int BT, int KSTEPS, int SUB, int AL, int BL, int F16>
__device__ __forceinline__ void mma_chunk(float acc[MI][4][4], u32 Ab, u32 Bb,
                                          int m0w, int n0w, int lane) {
    const int LO = 2 * SUB;
    #pragma unroll
    for (int ks = 0; ks < KSTEPS; ks++) {
        int k0 = ks * 16;
        u32 ah[MI][4], al[MI][4];
        #pragma unroll
        for (int mi = 0; mi < MI; mi++) {
            int m0 = m0w + mi * 16;
            u32 ad;
            if (AT) {
                int r = k0 + (lane & 7) + ((lane & 16) ? 8 : 0);
                int c = m0 + ((lane & 8) ? 8 : 0);
                ad = Ab + ((u32)(c >> 6)) * SUB + SWZ(r * 128 + (c & 63) * 2);
                ldsm4t(ad, ah[mi]); if (AL == 2) ldsm4t(ad + LO, al[mi]);
            } else {
                int r = m0 + (lane & 15);
                int c = k0 + ((lane >> 4) << 3);
                ad = Ab + SWZ(r * 128 + c * 2);
                ldsm4(ad, ah[mi]); if (AL == 2) ldsm4(ad + LO, al[mi]);
            }
        }
        u32 bh[4][2], bl[4][2];
        #pragma unroll
        for (int nj2 = 0; nj2 < 2; nj2++) {
            int n0 = n0w + nj2 * 16;
            u32 bd;
            u32 t[4], tl[4];
            if (BT) {
                int r = k0 + (lane & 7) + ((lane & 8) ? 8 : 0);
                int c = n0 + ((lane & 16) ? 8 : 0);
                bd = Bb + ((u32)(c >> 6)) * SUB + SWZ(r * 128 + (c & 63) * 2);
                ldsm4t(bd, t); if (BL == 2) ldsm4t(bd + LO, tl);
            } else {
                int r = n0 + (lane & 7) + ((lane & 16) ? 8 : 0);
                int c = k0 + ((lane & 8) ? 8 : 0);
                bd = Bb + SWZ(r * 128 + c * 2);
                ldsm4(bd, t); if (BL == 2) ldsm4(bd + LO, tl);
            }
            bh[nj2 * 2][0] = t[0];  bh[nj2 * 2][1] = t[1];
            bh[nj2 * 2 + 1][0] = t[2]; bh[nj2 * 2 + 1][1] = t[3];
            if (BL == 2) {
                bl[nj2 * 2][0] = tl[0]; bl[nj2 * 2][1] = tl[1];
                bl[nj2 * 2 + 1][0] = tl[2]; bl[nj2 * 2 + 1][1] = tl[3];
            }
        }
        #pragma unroll
        for (int mi = 0; mi < MI; mi++)
            #pragma unroll
            for (int nj = 0; nj < 4; nj++) {
                mmaop<F16>(acc[mi][nj], ah[mi], bh[nj][0], bh[nj][1]);
                if (BL == 2) mmaop<F16>(acc[mi][nj], ah[mi], bl[nj][0], bl[nj][1]);
                if (AL == 2) mmaop<F16>(acc[mi][nj], al[mi], bh[nj][0], bh[nj][1]);
            }
    }
}

// ---------------- dual-B warp MMA for k_AB: E 1L, Q 2L, T 1L (all fp16) ----
__device__ __forceinline__ void mma_chunk_dual(float accQ[2][4][4], float accT[2][4][4],
                                               u32 Ab, u32 Bq, u32 Bt,
                                               int m0w, int n0w, int lane) {
    #pragma unroll
    for (int ks = 0; ks < 4; ks++) {
        int k0 = ks * 16;
        u32 ah[2][4];
        #pragma unroll
        for (int mi = 0; mi < 2; mi++) {
            int m0 = m0w + mi * 16;
            int r = m0 + (lane & 15);
            int c = k0 + ((lane >> 4) << 3);
            ldsm4(Ab + SWZ(r * 128 + c * 2), ah[mi]);
        }
        // --- Q: natural 2-limb ---
        {
            u32 bh[4][2], bl[4][2];
            #pragma unroll
            for (int nj2 = 0; nj2 < 2; nj2++) {
                int n0 = n0w + nj2 * 16;
                int r = n0 + (lane & 7) + ((lane & 16) ? 8 : 0);
                int c = k0 + ((lane & 8) ? 8 : 0);
                u32 bd = Bq + SWZ(r * 128 + c * 2);
                u32 t[4], tl[4];
                ldsm4(bd, t); ldsm4(bd + 16384, tl);
                bh[nj2 * 2][0] = t[0];  bh[nj2 * 2][1] = t[1];
                bh[nj2 * 2 + 1][0] = t[2]; bh[nj2 * 2 + 1][1] = t[3];
                bl[nj2 * 2][0] = tl[0]; bl[nj2 * 2][1] = tl[1];
                bl[nj2 * 2 + 1][0] = tl[2]; bl[nj2 * 2 + 1][1] = tl[3];
            }
            #pragma unroll
            for (int mi = 0; mi < 2; mi++)
                #pragma unroll
                for (int nj = 0; nj < 4; nj++) {
                    mmaop<1>(accQ[mi][nj], ah[mi], bh[nj][0], bh[nj][1]);
                    mmaop<1>(accQ[mi][nj], ah[mi], bl[nj][0], bl[nj][1]);
                }
        }
        // --- T: k-major single-limb (SUB=8192) ---
        {
            u32 bh[4][2];
            #pragma unroll
            for (int nj2 = 0; nj2 < 2; nj2++) {
                int n0 = n0w + nj2 * 16;
                int r = k0 + (lane & 7) + ((lane & 8) ? 8 : 0);
                int c = n0 + ((lane & 16) ? 8 : 0);
                u32 bd = Bt + ((u32)(c >> 6)) * 8192 + SWZ(r * 128 + (c & 63) * 2);
                u32 t[4];
                ldsm4t(bd, t);
                bh[nj2 * 2][0] = t[0];  bh[nj2 * 2][1] = t[1];
                bh[nj2 * 2 + 1][0] = t[2]; bh[nj2 * 2 + 1][1] = t[3];
            }
            #pragma unroll
            for (int mi = 0; mi < 2; mi++)
                #pragma unroll
                for (int nj = 0; nj < 4; nj++)
                    mmaop<1>(accT[mi][nj], ah[mi], bh[nj][0], bh[nj][1]);
        }
    }
}

// =====================================================================
// k_cvtC: Cw planes + s0; C' planes; AND out section 0 (out[b][0:128] = C)
// =====================================================================
__global__ void __launch_bounds__(256) k_cvtC(const float* __restrict__ C,
                                              const int* __restrict__ Cmask,
                                              const float* __restrict__ w_mul,
                                              const float* __restrict__ w_c,
                                              const float* __restrict__ bias,
                                              float* __restrict__ out) {
    __shared__ float wc[128], wm[128], zb[512], s0s[128];
    int tid = threadIdx.x;
    int b = blockIdx.y, cB = blockIdx.x * 128;
    if (tid < 128) { wc[tid] = w_c[tid]; wm[tid] = w_mul[tid]; }
    __syncthreads();
    int cp = tid & 63, dq = tid >> 6;
    int c0 = cB + 2 * cp;
    int m0 = Cmask[b * LC_ + c0], m1 = Cmask[b * LC_ + c0 + 1];
    float s0e = 0.f, s0o = 0.f;
    float2 v[32];
    float* ob0 = out + (size_t)b * 4 * D_ * LC_;
    #pragma unroll
    for (int i = 0; i < 32; i++) {
        int d = dq * 32 + i;
        size_t gi = ((size_t)(b * D_ + d)) * LC_ + c0;
        v[i] = *(const float2*)(C + gi);
        s0e += v[i].x * wc[d]; s0o += v[i].y * wc[d];
        u32 h0, l0, h1, l1;
        splt(v[i].x * wm[d], h0, l0); splt(v[i].y * wm[d], h1, l1);
        g_Cwhi[gi >> 1] = h0 | (h1 << 16);
        g_Cwlo[gi >> 1] = l0 | (l1 << 16);
        *(float2*)(ob0 + (size_t)d * LC_ + c0) = v[i];   // section 0: out = C
    }
    zb[dq * 128 + 2 * cp] = s0e;
    zb[dq * 128 + 2 * cp + 1] = s0o;
    __syncthreads();
    if (tid < 128) {
        float s0 = zb[tid] + zb[128 + tid] + zb[256 + tid] + zb[384 + tid] + bias[0];
        g_s0[b * LC_ + cB + tid] = s0;
        s0s[tid] = s0;
    }
    __syncthreads();
    float Ma0 = m0 ? 16.f * __expf(s0s[2 * cp])     : 0.f;
    float Ma1 = m1 ? 16.f * __expf(s0s[2 * cp + 1]) : 0.f;
    #pragma unroll
    for (int i = 0; i < 32; i++) {
        int d = dq * 32 + i;
        size_t gi = ((size_t)(b * D_ + d)) * LC_ + c0;
        u32 h0, l0, h1, l1;
        splt16(v[i].x * Ma0, h0, l0); splt16(v[i].y * Ma1, h1, l1);
        g_Cfhi[gi >> 1] = h0 | (h1 << 16);
        g_Cflo[gi >> 1] = l0 | (l1 << 16);
    }
}

// =====================================================================
// k_cvtQ: Q -> bf16 2L (k_S) + fp16 2L (k_AB), fused s1
// =====================================================================
__global__ void __launch_bounds__(512) k_cvtQ(const float* __restrict__ Q,
                                              const float* __restrict__ w_q) {
    __shared__ float wq[128], zb[1024];
    int tid = threadIdx.x;
    int b = blockIdx.x;
    if (tid < 128) wq[tid] = w_q[tid];
    __syncthreads();
    int qp = tid & 255, dh = tid >> 8;
    int q0 = 2 * qp;
    float s1e = 0.f, s1o = 0.f;
    #pragma unroll 4
    for (int i = 0; i < 64; i++) {
        int d = dh * 64 + i;
        size_t gi = ((size_t)(b * D_ + d)) * LQ_ + q0;
        float2 v = *(const float2*)(Q + gi);
        s1e += v.x * wq[d]; s1o += v.y * wq[d];
        u32 h0, l0, h1, l1;
        splt(v.x, h0, l0); splt(v.y, h1, l1);
        g_Qhi[gi >> 1] = h0 | (h1 << 16);
        g_Qlo[gi >> 1] = l0 | (l1 << 16);
        splt16(v.x, h0, l0); splt16(v.y, h1, l1);
        g_Qfhi[gi >> 1] = h0 | (h1 << 16);
        g_Qflo[gi >> 1] = l0 | (l1 << 16);
    }
    zb[dh * 512 + q0]     = s1e;
    zb[dh * 512 + q0 + 1] = s1o;
    __syncthreads();
    g_s1[b * LQ_ + tid] = zb[tid] + zb[512 + tid];
}

// =====================================================================
// k_S: E'' = qmask*exp(s2+s1)/16 (fp16, 1 plane); Z1/Z2 partials.
//   exp computed on the FMA pipe (fexp16) — MUFU no longer the floor.
// =====================================================================
#define KS_S0 0
#define KS_S1 512
#define KS_QM 1024
#define KS_CM 1536
#define KS_ZS 2048
#define KS_ZC 4096
#define KS_BUF 8192
#define KS_DYN (8192 + 3 * 32768)

__global__ void __launch_bounds__(256, 2) k_S(const int* __restrict__ Qmask,
                                              const int* __restrict__ Cmask) {
    extern __shared__ char sm[];
    u32 sb = s2u(sm);
    int tid = threadIdx.x, lane = tid & 31, wid = tid >> 5;
    int b = blockIdx.z, cB = blockIdx.y * 128, qB = blockIdx.x * 128, qt = blockIdx.x;
    float* s0f = (float*)(sm + KS_S0);
    float* s1f = (float*)(sm + KS_S1);
    int*   qmi = (int*)(sm + KS_QM);
    float* cmk = (float*)(sm + KS_CM);
    float* zs  = (float*)(sm + KS_ZS);
    float* zc  = (float*)(sm + KS_ZC);
    if (tid < 128) {
        s0f[tid] = g_s0[b * LC_ + cB + tid];
        s1f[tid] = g_s1[b * LQ_ + qB + tid];
        qmi[tid] = Qmask[b * LQ_ + qB + tid];
        cmk[tid] = (float)Cmask[b * LC_ + cB + tid];
    }

    const __nv_bfloat16* CwH = (const __nv_bfloat16*)g_Cwhi;
    const __nv_bfloat16* CwL = (const __nv_bfloat16*)g_Cwlo;
    const __nv_bfloat16* QH  = (const __nv_bfloat16*)g_Qhi;
    const __nv_bfloat16* QL  = (const __nv_bfloat16*)g_Qlo;
    size_t Ca = (size_t)(b * D_) * LC_ + cB;
    size_t Qa = (size_t)(b * D_) * LQ_ + qB;

    #pragma unroll
    for (int pc = 0; pc < 2; pc++) {
        u32 st = sb + KS_BUF + pc * 32768;
        cpyT32<256, 2>(st,         CwH + Ca + (size_t)(pc * 32) * LC_, CwL + Ca + (size_t)(pc * 32) * LC_, LC_, tid);
        cpyT32<256, 2>(st + 16384, QH  + Qa + (size_t)(pc * 32) * LQ_, QL  + Qa + (size_t)(pc * 32) * LQ_, LQ_, tid);
        CP_COMMIT();
    }

    int wm = wid >> 2, wn = wid & 3;
    int m0w = wm * 64, n0w = wn * 32;
    float acc[4][4][4] = {};
    #pragma unroll
    for (int ci = 0; ci < 4; ci++) {
        if (ci < 3) CP_WAIT1(); else CP_WAIT0();
        __syncthreads();
        if (ci < 2) {
            int k0 = (ci + 2) * 32;
            u32 st = sb + KS_BUF + ((ci + 2) % 3) * 32768;
            cpyT32<256, 2>(st,         CwH + Ca + (size_t)k0 * LC_, CwL + Ca + (size_t)k0 * LC_, LC_, tid);
            cpyT32<256, 2>(st + 16384, QH  + Qa + (size_t)k0 * LQ_, QL  + Qa + (size_t)k0 * LQ_, LQ_, tid);
            CP_COMMIT();
        }
        u32 bb = sb + KS_BUF + (ci % 3) * 32768;
        mma_chunk<4, 1, 1, 2, 4096, 2, 2, 0>(acc, bb, bb + 16384, m0w, n0w, lane);
    }
    __syncthreads();

    int r = lane >> 2, cp = (lane & 3) * 2;
    float zrow[8] = {}, zcol[8] = {};
    u32 stg = sb + KS_BUF;
    #pragma unroll
    for (int mi = 0; mi < 4; mi++) {
        int m0 = m0w + mi * 16 + r;
        float cmaM = cmk[m0]     * 16.f * __expf(s0f[m0]);
        float cmbM = cmk[m0 + 8] * 16.f * __expf(s0f[m0 + 8]);
        #pragma unroll
        for (int nj = 0; nj < 4; nj++) {
            int q0 = n0w + nj * 8 + cp;
            float s1a = s1f[q0], s1b = s1f[q0 + 1];
            int qa = qmi[q0], qb = qmi[q0 + 1];
            float e00 = qa ? fexp16(acc[mi][nj][0] + s1a) : 0.f;
            float e01 = qb ? fexp16(acc[mi][nj][1] + s1b) : 0.f;
            float e10 = qa ? fexp16(acc[mi][nj][2] + s1a) : 0.f;
            float e11 = qb ? fexp16(acc[mi][nj][3] + s1b) : 0.f;
            zrow[mi * 2]     += e00 + e01;
            zrow[mi * 2 + 1] += e10 + e11;
            zcol[nj * 2]     += cmaM * e00 + cmbM * e10;
            zcol[nj * 2 + 1] += cmaM * e01 + cmbM * e11;
            u32 h00 = (u32)__half_as_ushort(__float2half(e00));
            u32 h01 = (u32)__half_as_ushort(__float2half(e01));
            u32 h10 = (u32)__half_as_ushort(__float2half(e10));
            u32 h11 = (u32)__half_as_ushort(__float2half(e11));
            sts32(stg + m0 * 272 + q0 * 2,       h00 | (h01 << 16));
            sts32(stg + (m0 + 8) * 272 + q0 * 2, h10 | (h11 << 16));
        }
    }
    #pragma unroll
    for (int h = 0; h < 8; h++) {
        float v = zrow[h];
        v += __shfl_xor_sync(0xffffffffu, v, 1);
        v += __shfl_xor_sync(0xffffffffu, v, 2);
        if ((lane & 3) == 0) {
            int m = m0w + (h >> 1) * 16 + ((h & 1) ? 8 : 0) + r;
            zs[m * 4 + wn] = v;
        }
    }
    #pragma unroll
    for (int j = 0; j < 8; j++) {
        float v = zcol[j];
        v += __shfl_xor_sync(0xffffffffu, v, 4);
        v += __shfl_xor_sync(0xffffffffu, v, 8);
        v += __shfl_xor_sync(0xffffffffu, v, 16);
        zcol[j] = v;
    }
    if (lane < 4) {
        #pragma unroll
        for (int nj = 0; nj < 4; nj++) {
            zc[wm * 128 + n0w + nj * 8 + lane * 2]     = zcol[nj * 2];
            zc[wm * 128 + n0w + nj * 8 + lane * 2 + 1] = zcol[nj * 2 + 1];
        }
    }
    __syncthreads();
    #pragma unroll
    for (int it = 0; it < 8; it++) {
        int idx = tid + it * 256;
        int chunk = idx & 15, c = idx >> 4;
        uint4 v = lds128(stg + c * 272 + chunk * 16);
        ((uint4*)g_E)[((((size_t)(b * LC_ + cB + c)) * LQ_ + qB) >> 3) + chunk] = v;
    }
    if (tid < 128) {
        g_Z1p[((size_t)b * LC_ + cB + tid) * 4 + qt] =
            zs[tid * 4] + zs[tid * 4 + 1] + zs[tid * 4 + 2] + zs[tid * 4 + 3];
        g_Z2p[((size_t)b * LQ_ + qB + tid) * 16 + blockIdx.y] = zc[tid] + zc[128 + tid];
    }
}

// =====================================================================
// k_T: T[q][d] = rZ2[q] * sum_c E''[c,q]*C'[d,c]; store fp16 single plane.
// =====================================================================
#define KT_RZ 0
#define KT_BUF 1024
#define KT_STAGE 49152
#define KT_DYN (1024 + 3 * KT_STAGE)

__global__ void __launch_bounds__(512, 1) k_T() {
    extern __shared__ char sm[];
    u32 sb = s2u(sm);
    int tid = threadIdx.x, lane = tid & 31, wid = tid >> 5;
    int b = blockIdx.y, qB = blockIdx.x * 128;
    float* rzs = (float*)(sm + KT_RZ);
    if (tid < 128) {
        const float* p = &g_Z2p[((size_t)b * LQ_ + qB + tid) * 16];
        float s = 0.f;
        #pragma unroll
        for (int t = 0; t < 16; t++) s += p[t];
        rzs[tid] = 1.f / fmaxf(s, 1e-30f);
    }
    const __half* EP = (const __half*)g_E;
    const __half* CH = (const __half*)g_Cfhi;
    const __half* CL = (const __half*)g_Cflo;
    size_t Eoff = (size_t)(b * LC_) * LQ_ + qB;
    size_t Coff = (size_t)(b * D_) * LC_;

    #pragma unroll
    for (int pc = 0; pc < 2; pc++) {
        u32 st = sb + KT_BUF + pc * KT_STAGE;
        cpyT64<512, 1>(st,          EP + Eoff + (size_t)(pc * 64) * LQ_, EP, LQ_, tid);
        cpyN128<512, 2>(st + 16384, CH + Coff + pc * 64, CL + Coff + pc * 64, LC_, tid);
        CP_COMMIT();
    }

    int wm = wid >> 2, wn = wid & 3;
    int m0w = wm * 32, n0w = wn * 32;
    float acc[2][4][4] = {};
    for (int ci = 0; ci < 32; ci++) {
        if (ci < 31) CP_WAIT1(); else CP_WAIT0();
        __syncthreads();
        if (ci < 30) {
            int c0 = (ci + 2) * 64;
            u32 st = sb + KT_BUF + ((ci + 2) % 3) * KT_STAGE;
            cpyT64<512, 1>(st,          EP + Eoff + (size_t)c0 * LQ_, EP, LQ_, tid);
            cpyN128<512, 2>(st + 16384, CH + Coff + c0, CL + Coff + c0, LC_, tid);
            CP_COMMIT();
        }
        u32 bb = sb + KT_BUF + (ci % 3) * KT_STAGE;
        mma_chunk<2, 1, 0, 4, 8192, 1, 2, 1>(acc, bb, bb + 16384, m0w, n0w, lane);
    }

    int r = lane >> 2, cp = (lane & 3) * 2;
    #pragma unroll
    for (int mi = 0; mi < 2; mi++) {
        int q0 = m0w + mi * 16 + r;
        float rza = rzs[q0], rzb = rzs[q0 + 8];
        #pragma unroll
        for (int nj = 0; nj < 4; nj++) {
            int d0 = n0w + nj * 8 + cp;
            size_t i0 = ((size_t)(b * LQ_ + qB + q0) * D_ + d0) >> 1;
            size_t i1 = ((size_t)(b * LQ_ + qB + q0 + 8) * D_ + d0) >> 1;
            u32 h0 = (u32)__half_as_ushort(__float2half(acc[mi][nj][0] * rza));
            u32 h1 = (u32)__half_as_ushort(__float2half(acc[mi][nj][1] * rza));
            g_T[i0] = h0 | (h1 << 16);
            h0 = (u32)__half_as_ushort(__float2half(acc[mi][nj][2] * rzb));
            h1 = (u32)__half_as_ushort(__float2half(acc[mi][nj][3] * rzb));
            g_T[i1] = h0 | (h1 << 16);
        }
    }
}

// =====================================================================
// k_AB: accQ = E''@Qf (2L), accT = E''@T (1L) in one K sweep.
// =====================================================================
#define KA_RZ 0
#define KA_BUF 1024
#define KA_STAGE 65536
#define KA_DYN (1024 + 3 * KA_STAGE)

__global__ void __launch_bounds__(512, 1) k_AB(const float* __restrict__ C,
                                               float* __restrict__ out) {
    extern __shared__ char sm[];
    u32 sb = s2u(sm);
    int tid = threadIdx.x, lane = tid & 31, wid = tid >> 5;
    int b = blockIdx.y, cB = blockIdx.x * 128;
    float* rzs = (float*)(sm + KA_RZ);
    if (tid < 128) {
        const float* p = &g_Z1p[((size_t)b * LC_ + cB + tid) * 4];
        rzs[tid] = 1.f / (p[0] + p[1] + p[2] + p[3]);
    }
    const __half* EP = (const __half*)g_E;
    const __half* QH = (const __half*)g_Qfhi;
    const __half* QL = (const __half*)g_Qflo;
    const __half* TP = (const __half*)g_T;
    size_t Eoff = ((size_t)b * LC_ + cB) * LQ_;
    size_t Qoff = (size_t)(b * D_) * LQ_;
    size_t Toff = (size_t)(b * LQ_) * D_;
    const float* Cb = C + (size_t)b * D_ * LC_ + cB;
    float* ob = out + (size_t)b * 4 * D_ * LC_ + cB;
    float* stgQ = (float*)(sm + KA_BUF);
    float* stgT = stgQ + 128 * 132;
    int wm = wid >> 2, wn = wid & 3;
    int m0w = wm * 32, n0w = wn * 32;
    int r = lane >> 2, cp = (lane & 3) * 2;

    #pragma unroll
    for (int pc = 0; pc < 2; pc++) {
        int q0 = pc * 64;
        u32 st = sb + KA_BUF + pc * KA_STAGE;
        cpyN128<512, 1>(st,         EP + Eoff + q0, EP, LQ_, tid);
        cpyN128<512, 2>(st + 16384, QH + Qoff + q0, QL + Qoff + q0, LQ_, tid);
        cpyT64<512, 1> (st + 49152, TP + Toff + (size_t)q0 * D_, TP, D_, tid);
        CP_COMMIT();
    }

    float accQ[2][4][4] = {}, accT[2][4][4] = {};
    for (int ci = 0; ci < 8; ci++) {
        if (ci < 7) CP_WAIT1(); else CP_WAIT0();
        __syncthreads();
        if (ci < 6) {
            int q0 = (ci + 2) * 64;
            u32 st = sb + KA_BUF + ((ci + 2) % 3) * KA_STAGE;
            cpyN128<512, 1>(st,         EP + Eoff + q0, EP, LQ_, tid);
            cpyN128<512, 2>(st + 16384, QH + Qoff + q0, QL + Qoff + q0, LQ_, tid);
            cpyT64<512, 1> (st + 49152, TP + Toff + (size_t)q0 * D_, TP, D_, tid);
            CP_COMMIT();
        }
        u32 bb = sb + KA_BUF + (ci % 3) * KA_STAGE;
        mma_chunk_dual(accQ, accT, bb, bb + 16384, bb + 49152, m0w, n0w, lane);
    }
    __syncthreads();

    #pragma unroll
    for (int mi = 0; mi < 2; mi++) {
        int m0 = m0w + mi * 16 + r;
        float rza = rzs[m0], rzb = rzs[m0 + 8];
        #pragma unroll
        for (int nj = 0; nj < 4; nj++) {
            int n0 = n0w + nj * 8 + cp;
            stgQ[n0 * 132 + m0]           = accQ[mi][nj][0] * rza;
            stgQ[(n0 + 1) * 132 + m0]     = accQ[mi][nj][1] * rza;
            stgQ[n0 * 132 + m0 + 8]       = accQ[mi][nj][2] * rzb;
            stgQ[(n0 + 1) * 132 + m0 + 8] = accQ[mi][nj][3] * rzb;
            stgT[n0 * 132 + m0]           = accT[mi][nj][0] * rza;
            stgT[(n0 + 1) * 132 + m0]     = accT[mi][nj][1] * rza;
            stgT[n0 * 132 + m0 + 8]       = accT[mi][nj][2] * rzb;
            stgT[(n0 + 1) * 132 + m0 + 8] = accT[mi][nj][3] * rzb;
        }
    }
    __syncthreads();
    for (int idx = tid; idx < 128 * 128; idx += 512) {
        int dd = idx >> 7, c = idx & 127;
        float a  = stgQ[dd * 132 + c];
        float bm = stgT[dd * 132 + c];
        float cv = Cb[(size_t)dd * LC_ + c];
        ob[(size_t)(128 + dd) * LC_ + c] = a;
        ob[(size_t)(256 + dd) * LC_ + c] = cv * a;
        ob[(size_t)(384 + dd) * LC_ + c] = cv * bm;
    }
}

// =====================================================================
extern "C" void kernel_launch(void* const* d_in, const int* in_sizes, int n_in,
                              void* d_out, int out_size) {
    const float* C     = (const float*)d_in[0];
    const float* Q     = (const float*)d_in[1];
    const int*   Cmask = (const int*)  d_in[2];
    const int*   Qmask = (const int*)  d_in[3];
    const float* w_c   = (const float*)d_in[4];
    const float* w_q   = (const float*)d_in[5];
    const float* w_mul = (const float*)d_in[6];
    const float* bias  = (const float*)d_in[7];
    float* out = (float*)d_out;

    cudaFuncSetAttribute(k_S,  cudaFuncAttributeMaxDynamicSharedMemorySize, KS_DYN);
    cudaFuncSetAttribute(k_T,  cudaFuncAttributeMaxDynamicSharedMemorySize, KT_DYN);
    cudaFuncSetAttribute(k_AB, cudaFuncAttributeMaxDynamicSharedMemorySize, KA_DYN);

    k_cvtC<<<dim3(16, 32), 256>>>(C, Cmask, w_mul, w_c, bias, out);
    k_cvtQ<<<32, 512>>>(Q, w_q);
    k_S<<<dim3(4, 16, 32), 256, KS_DYN>>>(Qmask, Cmask);
    k_T<<<dim3(4, 32), 512, KT_DYN>>>();
    k_AB<<<dim3(16, 32), 512, KA_DYN>>>(C, out);
}

// round 17
// speedup vs baseline: 1.2397x; 1.2397x over previous
#include <cuda_runtime.h>
#include <cuda_bf16.h>
#include <cuda_fp16.h>
#include <cstdint>

#define B_   32
#define D_   128
#define LC_  2048
#define LQ_  512

typedef unsigned int u32;

// ---------------- scratch planes ----------------
__device__ u32 g_E[(size_t)B_ * LC_ * LQ_ / 2];        // E'' fp16 single plane
__device__ u32 g_Cwhi[(size_t)B_ * D_ * LC_ / 2];      // C*w_mul bf16 2L (k_S)
__device__ u32 g_Cwlo[(size_t)B_ * D_ * LC_ / 2];
__device__ u32 g_Cf[(size_t)B_ * D_ * LC_ / 2];        // C' = C*cmask*16*exp(s0), fp16 1L
__device__ u32 g_Qhi[(size_t)B_ * D_ * LQ_ / 2];       // Q bf16 2L (k_S)
__device__ u32 g_Qlo[(size_t)B_ * D_ * LQ_ / 2];
__device__ u32 g_Qf[(size_t)B_ * D_ * LQ_ / 2];        // Q fp16 1L (k_AB)
__device__ u32 g_T[(size_t)B_ * LQ_ * D_ / 2];         // T fp16 single plane
__device__ float g_s0[B_ * LC_];
__device__ float g_s1[B_ * LQ_];
__device__ float g_Z1p[B_ * LC_ * 4];
__device__ float g_Z2p[B_ * LQ_ * 16];

// ---------------- helpers ----------------
__device__ __forceinline__ u32 s2u(const void* p) {
    u32 a; asm("{ .reg .u64 t; cvta.to.shared.u64 t, %1; cvt.u32.u64 %0, t; }" : "=r"(a) : "l"(p));
    return a;
}
#define SWZ(x) ((u32)(x) ^ ((((u32)(x)) >> 3) & 0x70))

__device__ __forceinline__ void cpa16(u32 dst, const void* src) {
    asm volatile("cp.async.cg.shared.global [%0], [%1], 16;" :: "r"(dst), "l"(src));
}
#define CP_COMMIT() asm volatile("cp.async.commit_group;")
#define CP_WAIT0()  asm volatile("cp.async.wait_group 0;")
#define CP_WAIT1()  asm volatile("cp.async.wait_group 1;")

__device__ __forceinline__ void splt(float v, u32 &hi, u32 &lo) {     // bf16 2-limb
    __nv_bfloat16 h = __float2bfloat16(v);
    __nv_bfloat16 l = __float2bfloat16(v - __bfloat162float(h));
    hi = (u32)__bfloat16_as_ushort(h);
    lo = (u32)__bfloat16_as_ushort(l);
}
__device__ __forceinline__ u32 h16(float v) {
    return (u32)__half_as_ushort(__float2half(v));
}

__device__ __forceinline__ void ldsm4(u32 addr, u32 r[4]) {
    asm volatile("ldmatrix.sync.aligned.m8n8.x4.shared.b16 {%0,%1,%2,%3}, [%4];"
                 : "=r"(r[0]), "=r"(r[1]), "=r"(r[2]), "=r"(r[3]) : "r"(addr));
}
__device__ __forceinline__ void ldsm4t(u32 addr, u32 r[4]) {
    asm volatile("ldmatrix.sync.aligned.m8n8.x4.trans.shared.b16 {%0,%1,%2,%3}, [%4];"
                 : "=r"(r[0]), "=r"(r[1]), "=r"(r[2]), "=r"(r[3]) : "r"(addr));
}
template<int F16>
__device__ __forceinline__ void mmaop(float d[4], const u32 a[4], u32 b0, u32 b1) {
    if (F16)
        asm volatile("mma.sync.aligned.m16n8k16.row.col.f32.f16.f16.f32 "
                     "{%0,%1,%2,%3}, {%4,%5,%6,%7}, {%8,%9}, {%0,%1,%2,%3};"
                     : "+f"(d[0]), "+f"(d[1]), "+f"(d[2]), "+f"(d[3])
                     : "r"(a[0]), "r"(a[1]), "r"(a[2]), "r"(a[3]), "r"(b0), "r"(b1));
    else
        asm volatile("mma.sync.aligned.m16n8k16.row.col.f32.bf16.bf16.f32 "
                     "{%0,%1,%2,%3}, {%4,%5,%6,%7}, {%8,%9}, {%0,%1,%2,%3};"
                     : "+f"(d[0]), "+f"(d[1]), "+f"(d[2]), "+f"(d[3])
                     : "r"(a[0]), "r"(a[1]), "r"(a[2]), "r"(a[3]), "r"(b0), "r"(b1));
}
__device__ __forceinline__ uint4 lds128(u32 a) {
    uint4 v;
    asm volatile("ld.shared.v4.b32 {%0,%1,%2,%3}, [%4];"
                 : "=r"(v.x), "=r"(v.y), "=r"(v.z), "=r"(v.w) : "r"(a));
    return v;
}
__device__ __forceinline__ void sts32(u32 a, u32 v) { asm volatile("st.shared.b32 [%0], %1;" :: "r"(a), "r"(v)); }

// ---------------- chunk copies (L = limb count) ----------------
template<int NT, int L, typename H>
__device__ __forceinline__ void cpyT64(u32 dstBase, const H* srcHi, const H* srcLo,
                                       size_t rowStride, int tid) {
    #pragma unroll
    for (int t = 0; t < (1024 * L) / NT; t++) {
        int u = tid + t * NT;
        int limb = u >> 10, rem = u & 1023;
        int row = rem >> 4, ucol = rem & 15;
        const H* src = (limb ? srcLo : srcHi) + (size_t)row * rowStride + ucol * 8;
        u32 dst = dstBase + limb * 16384 + (ucol >> 3) * 8192 + SWZ(row * 128 + (ucol & 7) * 16);
        cpa16(dst, src);
    }
}
template<int NT, int L, typename H>
__device__ __forceinline__ void cpyT32(u32 dstBase, const H* srcHi, const H* srcLo,
                                       size_t rowStride, int tid) {
    #pragma unroll
    for (int t = 0; t < (512 * L) / NT; t++) {
        int u = tid + t * NT;
        int limb = u >> 9, rem = u & 511;
        int row = rem >> 4, ucol = rem & 15;
        const H* src = (limb ? srcLo : srcHi) + (size_t)row * rowStride + ucol * 8;
        u32 dst = dstBase + limb * 8192 + (ucol >> 3) * 4096 + SWZ(row * 128 + (ucol & 7) * 16);
        cpa16(dst, src);
    }
}
template<int NT, int L, typename H>
__device__ __forceinline__ void cpyN128(u32 dstBase, const H* srcHi, const H* srcLo,
                                        size_t rowStride, int tid) {
    #pragma unroll
    for (int t = 0; t < (1024 * L) / NT; t++) {
        int u = tid + t * NT;
        int limb = u >> 10, rem = u & 1023;
        int row = rem >> 3, ucol = rem & 7;
        const H* src = (limb ? srcLo : srcHi) + (size_t)row * rowStride + ucol * 8;
        u32 dst = dstBase + limb * 16384 + SWZ(row * 128 + ucol * 16);
        cpa16(dst, src);
    }
}

// ---------------- warp MMA over one chunk ----------------------------------
template<int MI, int AT, int BT, int KSTEPS, int SUB, int AL, int BL, int F16>
__device__ __forceinline__ void mma_chunk(float acc[MI][4][4], u32 Ab, u32 Bb,
                                          int m0w, int n0w, int lane) {
    const int LO = 2 * SUB;
    #pragma unroll
    for (int ks = 0; ks < KSTEPS; ks++) {
        int k0 = ks * 16;
        u32 ah[MI][4], al[MI][4];
        #pragma unroll
        for (int mi = 0; mi < MI; mi++) {
            int m0 = m0w + mi * 16;
            u32 ad;
            if (AT) {
                int r = k0 + (lane & 7) + ((lane & 16) ? 8 : 0);
                int c = m0 + ((lane & 8) ? 8 : 0);
                ad = Ab + ((u32)(c >> 6)) * SUB + SWZ(r * 128 + (c & 63) * 2);
                ldsm4t(ad, ah[mi]); if (AL == 2) ldsm4t(ad + LO, al[mi]);
            } else {
                int r = m0 + (lane & 15);
                int c = k0 + ((lane >> 4) << 3);
                ad = Ab + SWZ(r * 128 + c * 2);
                ldsm4(ad, ah[mi]); if (AL == 2) ldsm4(ad + LO, al[mi]);
            }
        }
        u32 bh[4][2], bl[4][2];
        #pragma unroll
        for (int nj2 = 0; nj2 < 2; nj2++) {
            int n0 = n0w + nj2 * 16;
            u32 bd;
            u32 t[4], tl[4];
            if (BT) {
                int r = k0 + (lane & 7) + ((lane & 8) ? 8 : 0);
                int c = n0 + ((lane & 16) ? 8 : 0);
                bd = Bb + ((u32)(c >> 6)) * SUB + SWZ(r * 128 + (c & 63) * 2);
                ldsm4t(bd, t); if (BL == 2) ldsm4t(bd + LO, tl);
            } else {
                int r = n0 + (lane & 7) + ((lane & 16) ? 8 : 0);
                int c = k0 + ((lane & 8) ? 8 : 0);
                bd = Bb + SWZ(r * 128 + c * 2);
                ldsm4(bd, t); if (BL == 2) ldsm4(bd + LO, tl);
            }
            bh[nj2 * 2][0] = t[0];  bh[nj2 * 2][1] = t[1];
            bh[nj2 * 2 + 1][0] = t[2]; bh[nj2 * 2 + 1][1] = t[3];
            if (BL == 2) {
                bl[nj2 * 2][0] = tl[0]; bl[nj2 * 2][1] = tl[1];
                bl[nj2 * 2 + 1][0] = tl[2]; bl[nj2 * 2 + 1][1] = tl[3];
            }
        }
        #pragma unroll
        for (int mi = 0; mi < MI; mi++)
            #pragma unroll
            for (int nj = 0; nj < 4; nj++) {
                mmaop<F16>(acc[mi][nj], ah[mi], bh[nj][0], bh[nj][1]);
                if (BL == 2) mmaop<F16>(acc[mi][nj], ah[mi], bl[nj][0], bl[nj][1]);
                if (AL == 2) mmaop<F16>(acc[mi][nj], al[mi], bh[nj][0], bh[nj][1]);
            }
    }
}

// ---------------- dual-B warp MMA for k_AB: E 1L, Q 1L, T 1L (all fp16) ----
__device__ __forceinline__ void mma_chunk_dual(float accQ[2][4][4], float accT[2][4][4],
                                               u32 Ab, u32 Bq, u32 Bt,
                                               int m0w, int n0w, int lane) {
    #pragma unroll
    for (int ks = 0; ks < 4; ks++) {
        int k0 = ks * 16;
        u32 ah[2][4];
        #pragma unroll
        for (int mi = 0; mi < 2; mi++) {
            int m0 = m0w + mi * 16;
            int r = m0 + (lane & 15);
            int c = k0 + ((lane >> 4) << 3);
            ldsm4(Ab + SWZ(r * 128 + c * 2), ah[mi]);
        }
        // --- Q: natural 1-limb ---
        {
            u32 bh[4][2];
            #pragma unroll
            for (int nj2 = 0; nj2 < 2; nj2++) {
                int n0 = n0w + nj2 * 16;
                int r = n0 + (lane & 7) + ((lane & 16) ? 8 : 0);
                int c = k0 + ((lane & 8) ? 8 : 0);
                u32 t[4];
                ldsm4(Bq + SWZ(r * 128 + c * 2), t);
                bh[nj2 * 2][0] = t[0];  bh[nj2 * 2][1] = t[1];
                bh[nj2 * 2 + 1][0] = t[2]; bh[nj2 * 2 + 1][1] = t[3];
            }
            #pragma unroll
            for (int mi = 0; mi < 2; mi++)
                #pragma unroll
                for (int nj = 0; nj < 4; nj++)
                    mmaop<1>(accQ[mi][nj], ah[mi], bh[nj][0], bh[nj][1]);
        }
        // --- T: k-major single-limb (SUB=8192) ---
        {
            u32 bh[4][2];
            #pragma unroll
            for (int nj2 = 0; nj2 < 2; nj2++) {
                int n0 = n0w + nj2 * 16;
                int r = k0 + (lane & 7) + ((lane & 8) ? 8 : 0);
                int c = n0 + ((lane & 16) ? 8 : 0);
                u32 t[4];
                ldsm4t(Bt + ((u32)(c >> 6)) * 8192 + SWZ(r * 128 + (c & 63) * 2), t);
                bh[nj2 * 2][0] = t[0];  bh[nj2 * 2][1] = t[1];
                bh[nj2 * 2 + 1][0] = t[2]; bh[nj2 * 2 + 1][1] = t[3];
            }
            #pragma unroll
            for (int mi = 0; mi < 2; mi++)
                #pragma unroll
                for (int nj = 0; nj < 4; nj++)
                    mmaop<1>(accT[mi][nj], ah[mi], bh[nj][0], bh[nj][1]);
        }
    }
}

// =====================================================================
// k_cvtC: Cw planes + s0; C' 1L; out section 0 (out = C)
// =====================================================================
__global__ void __launch_bounds__(256) k_cvtC(const float* __restrict__ C,
                                              const int* __restrict__ Cmask,
                                              const float* __restrict__ w_mul,
                                              const float* __restrict__ w_c,
                                              const float* __restrict__ bias,
                                              float* __restrict__ out) {
    __shared__ float wc[128], wm[128], zb[512], s0s[128];
    int tid = threadIdx.x;
    int b = blockIdx.y, cB = blockIdx.x * 128;
    if (tid < 128) { wc[tid] = w_c[tid]; wm[tid] = w_mul[tid]; }
    __syncthreads();
    int cp = tid & 63, dq = tid >> 6;
    int c0 = cB + 2 * cp;
    int m0 = Cmask[b * LC_ + c0], m1 = Cmask[b * LC_ + c0 + 1];
    float s0e = 0.f, s0o = 0.f;
    float2 v[32];
    float* ob0 = out + (size_t)b * 4 * D_ * LC_;
    #pragma unroll
    for (int i = 0; i < 32; i++) {
        int d = dq * 32 + i;
        size_t gi = ((size_t)(b * D_ + d)) * LC_ + c0;
        v[i] = *(const float2*)(C + gi);
        s0e += v[i].x * wc[d]; s0o += v[i].y * wc[d];
        u32 h0, l0, h1, l1;
        splt(v[i].x * wm[d], h0, l0); splt(v[i].y * wm[d], h1, l1);
        g_Cwhi[gi >> 1] = h0 | (h1 << 16);
        g_Cwlo[gi >> 1] = l0 | (l1 << 16);
        *(float2*)(ob0 + (size_t)d * LC_ + c0) = v[i];   // section 0
    }
    zb[dq * 128 + 2 * cp] = s0e;
    zb[dq * 128 + 2 * cp + 1] = s0o;
    __syncthreads();
    if (tid < 128) {
        float s0 = zb[tid] + zb[128 + tid] + zb[256 + tid] + zb[384 + tid] + bias[0];
        g_s0[b * LC_ + cB + tid] = s0;
        s0s[tid] = s0;
    }
    __syncthreads();
    float Ma0 = m0 ? 16.f * __expf(s0s[2 * cp])     : 0.f;
    float Ma1 = m1 ? 16.f * __expf(s0s[2 * cp + 1]) : 0.f;
    #pragma unroll
    for (int i = 0; i < 32; i++) {
        int d = dq * 32 + i;
        size_t gi = ((size_t)(b * D_ + d)) * LC_ + c0;
        g_Cf[gi >> 1] = h16(v[i].x * Ma0) | (h16(v[i].y * Ma1) << 16);
    }
}

// =====================================================================
// k_cvtQ: Q -> bf16 2L (k_S) + fp16 1L (k_AB), fused s1
// =====================================================================
__global__ void __launch_bounds__(512) k_cvtQ(const float* __restrict__ Q,
                                              const float* __restrict__ w_q) {
    __shared__ float wq[128], zb[1024];
    int tid = threadIdx.x;
    int b = blockIdx.x;
    if (tid < 128) wq[tid] = w_q[tid];
    __syncthreads();
    int qp = tid & 255, dh = tid >> 8;
    int q0 = 2 * qp;
    float s1e = 0.f, s1o = 0.f;
    #pragma unroll 4
    for (int i = 0; i < 64; i++) {
        int d = dh * 64 + i;
        size_t gi = ((size_t)(b * D_ + d)) * LQ_ + q0;
        float2 v = *(const float2*)(Q + gi);
        s1e += v.x * wq[d]; s1o += v.y * wq[d];
        u32 h0, l0, h1, l1;
        splt(v.x, h0, l0); splt(v.y, h1, l1);
        g_Qhi[gi >> 1] = h0 | (h1 << 16);
        g_Qlo[gi >> 1] = l0 | (l1 << 16);
        g_Qf[gi >> 1] = h16(v.x) | (h16(v.y) << 16);
    }
    zb[dh * 512 + q0]     = s1e;
    zb[dh * 512 + q0 + 1] = s1o;
    __syncthreads();
    g_s1[b * LQ_ + tid] = zb[tid] + zb[512 + tid];
}

// =====================================================================
// k_S: E'' = qmask*exp(s2+s1)/16 (fp16, 1 plane); Z1/Z2 partials.
// =====================================================================
#define KS_S0 0
#define KS_S1 512
#define KS_QM 1024
#define KS_CM 1536
#define KS_ZS 2048
#define KS_ZC 4096
#define KS_BUF 8192
#define KS_DYN (8192 + 3 * 32768)

__global__ void __launch_bounds__(256, 2) k_S(const int* __restrict__ Qmask,
                                              const int* __restrict__ Cmask) {
    extern __shared__ char sm[];
    u32 sb = s2u(sm);
    int tid = threadIdx.x, lane = tid & 31, wid = tid >> 5;
    int b = blockIdx.z, cB = blockIdx.y * 128, qB = blockIdx.x * 128, qt = blockIdx.x;
    float* s0f = (float*)(sm + KS_S0);
    float* s1f = (float*)(sm + KS_S1);
    int*   qmi = (int*)(sm + KS_QM);
    float* cmk = (float*)(sm + KS_CM);
    float* zs  = (float*)(sm + KS_ZS);
    float* zc  = (float*)(sm + KS_ZC);
    if (tid < 128) {
        s0f[tid] = g_s0[b * LC_ + cB + tid];
        s1f[tid] = g_s1[b * LQ_ + qB + tid];
        qmi[tid] = Qmask[b * LQ_ + qB + tid];
        cmk[tid] = (float)Cmask[b * LC_ + cB + tid];
    }

    const __nv_bfloat16* CwH = (const __nv_bfloat16*)g_Cwhi;
    const __nv_bfloat16* CwL = (const __nv_bfloat16*)g_Cwlo;
    const __nv_bfloat16* QH  = (const __nv_bfloat16*)g_Qhi;
    const __nv_bfloat16* QL  = (const __nv_bfloat16*)g_Qlo;
    size_t Ca = (size_t)(b * D_) * LC_ + cB;
    size_t Qa = (size_t)(b * D_) * LQ_ + qB;

    #pragma unroll
    for (int pc = 0; pc < 2; pc++) {
        u32 st = sb + KS_BUF + pc * 32768;
        cpyT32<256, 2>(st,         CwH + Ca + (size_t)(pc * 32) * LC_, CwL + Ca + (size_t)(pc * 32) * LC_, LC_, tid);
        cpyT32<256, 2>(st + 16384, QH  + Qa + (size_t)(pc * 32) * LQ_, QL  + Qa + (size_t)(pc * 32) * LQ_, LQ_, tid);
        CP_COMMIT();
    }

    int wm = wid >> 2, wn = wid & 3;
    int m0w = wm * 64, n0w = wn * 32;
    float acc[4][4][4] = {};
    #pragma unroll
    for (int ci = 0; ci < 4; ci++) {
        if (ci < 3) CP_WAIT1(); else CP_WAIT0();
        __syncthreads();
        if (ci < 2) {
            int k0 = (ci + 2) * 32;
            u32 st = sb + KS_BUF + ((ci + 2) % 3) * 32768;
            cpyT32<256, 2>(st,         CwH + Ca + (size_t)k0 * LC_, CwL + Ca + (size_t)k0 * LC_, LC_, tid);
            cpyT32<256, 2>(st + 16384, QH  + Qa + (size_t)k0 * LQ_, QL  + Qa + (size_t)k0 * LQ_, LQ_, tid);
            CP_COMMIT();
        }
        u32 bb = sb + KS_BUF + (ci % 3) * 32768;
        mma_chunk<4, 1, 1, 2, 4096, 2, 2, 0>(acc, bb, bb + 16384, m0w, n0w, lane);
    }
    __syncthreads();

    int r = lane >> 2, cp = (lane & 3) * 2;
    float zrow[8] = {}, zcol[8] = {};
    u32 stg = sb + KS_BUF;
    #pragma unroll
    for (int mi = 0; mi < 4; mi++) {
        int m0 = m0w + mi * 16 + r;
        float cmaM = cmk[m0]     * 16.f * __expf(s0f[m0]);
        float cmbM = cmk[m0 + 8] * 16.f * __expf(s0f[m0 + 8]);
        #pragma unroll
        for (int nj = 0; nj < 4; nj++) {
            int q0 = n0w + nj * 8 + cp;
            float s1a = s1f[q0], s1b = s1f[q0 + 1];
            int qa = qmi[q0], qb = qmi[q0 + 1];
            float e00 = qa ? __expf(acc[mi][nj][0] + s1a) * 0.0625f : 0.f;
            float e01 = qb ? __expf(acc[mi][nj][1] + s1b) * 0.0625f : 0.f;
            float e10 = qa ? __expf(acc[mi][nj][2] + s1a) * 0.0625f : 0.f;
            float e11 = qb ? __expf(acc[mi][nj][3] + s1b) * 0.0625f : 0.f;
            zrow[mi * 2]     += e00 + e01;
            zrow[mi * 2 + 1] += e10 + e11;
            zcol[nj * 2]     += cmaM * e00 + cmbM * e10;
            zcol[nj * 2 + 1] += cmaM * e01 + cmbM * e11;
            sts32(stg + m0 * 272 + q0 * 2,       h16(e00) | (h16(e01) << 16));
            sts32(stg + (m0 + 8) * 272 + q0 * 2, h16(e10) | (h16(e11) << 16));
        }
    }
    #pragma unroll
    for (int h = 0; h < 8; h++) {
        float v = zrow[h];
        v += __shfl_xor_sync(0xffffffffu, v, 1);
        v += __shfl_xor_sync(0xffffffffu, v, 2);
        if ((lane & 3) == 0) {
            int m = m0w + (h >> 1) * 16 + ((h & 1) ? 8 : 0) + r;
            zs[m * 4 + wn] = v;
        }
    }
    #pragma unroll
    for (int j = 0; j < 8; j++) {
        float v = zcol[j];
        v += __shfl_xor_sync(0xffffffffu, v, 4);
        v += __shfl_xor_sync(0xffffffffu, v, 8);
        v += __shfl_xor_sync(0xffffffffu, v, 16);
        zcol[j] = v;
    }
    if (lane < 4) {
        #pragma unroll
        for (int nj = 0; nj < 4; nj++) {
            zc[wm * 128 + n0w + nj * 8 + lane * 2]     = zcol[nj * 2];
            zc[wm * 128 + n0w + nj * 8 + lane * 2 + 1] = zcol[nj * 2 + 1];
        }
    }
    __syncthreads();
    #pragma unroll
    for (int it = 0; it < 8; it++) {
        int idx = tid + it * 256;
        int chunk = idx & 15, c = idx >> 4;
        uint4 v = lds128(stg + c * 272 + chunk * 16);
        ((uint4*)g_E)[((((size_t)(b * LC_ + cB + c)) * LQ_ + qB) >> 3) + chunk] = v;
    }
    if (tid < 128) {
        g_Z1p[((size_t)b * LC_ + cB + tid) * 4 + qt] =
            zs[tid * 4] + zs[tid * 4 + 1] + zs[tid * 4 + 2] + zs[tid * 4 + 3];
        g_Z2p[((size_t)b * LQ_ + qB + tid) * 16 + blockIdx.y] = zc[tid] + zc[128 + tid];
    }
}

// =====================================================================
// k_T: T = rZ2 * (E''^T @ C'^T); all 1-limb fp16 (1 MMA term).
// =====================================================================
#define KT_RZ 0
#define KT_BUF 1024
#define KT_STAGE 32768
#define KT_DYN (1024 + 3 * KT_STAGE)

__global__ void __launch_bounds__(512, 1) k_T() {
    extern __shared__ char sm[];
    u32 sb = s2u(sm);
    int tid = threadIdx.x, lane = tid & 31, wid = tid >> 5;
    int b = blockIdx.y, qB = blockIdx.x * 128;
    float* rzs = (float*)(sm + KT_RZ);
    if (tid < 128) {
        const float* p = &g_Z2p[((size_t)b * LQ_ + qB + tid) * 16];
        float s = 0.f;
        #pragma unroll
        for (int t = 0; t < 16; t++) s += p[t];
        rzs[tid] = 1.f / fmaxf(s, 1e-30f);
    }
    const __half* EP = (const __half*)g_E;
    const __half* CP = (const __half*)g_Cf;
    size_t Eoff = (size_t)(b * LC_) * LQ_ + qB;
    size_t Coff = (size_t)(b * D_) * LC_;

    #pragma unroll
    for (int pc = 0; pc < 2; pc++) {
        u32 st = sb + KT_BUF + pc * KT_STAGE;
        cpyT64<512, 1>(st,          EP + Eoff + (size_t)(pc * 64) * LQ_, EP, LQ_, tid);
        cpyN128<512, 1>(st + 16384, CP + Coff + pc * 64, CP, LC_, tid);
        CP_COMMIT();
    }

    int wm = wid >> 2, wn = wid & 3;
    int m0w = wm * 32, n0w = wn * 32;
    float acc[2][4][4] = {};
    for (int ci = 0; ci < 32; ci++) {
        if (ci < 31) CP_WAIT1(); else CP_WAIT0();
        __syncthreads();
        if (ci < 30) {
            int c0 = (ci + 2) * 64;
            u32 st = sb + KT_BUF + ((ci + 2) % 3) * KT_STAGE;
            cpyT64<512, 1>(st,          EP + Eoff + (size_t)c0 * LQ_, EP, LQ_, tid);
            cpyN128<512, 1>(st + 16384, CP + Coff + c0, CP, LC_, tid);
            CP_COMMIT();
        }
        u32 bb = sb + KT_BUF + (ci % 3) * KT_STAGE;
        mma_chunk<2, 1, 0, 4, 8192, 1, 1, 1>(acc, bb, bb + 16384, m0w, n0w, lane);
    }

    int r = lane >> 2, cp = (lane & 3) * 2;
    #pragma unroll
    for (int mi = 0; mi < 2; mi++) {
        int q0 = m0w + mi * 16 + r;
        float rza = rzs[q0], rzb = rzs[q0 + 8];
        #pragma unroll
        for (int nj = 0; nj < 4; nj++) {
            int d0 = n0w + nj * 8 + cp;
            size_t i0 = ((size_t)(b * LQ_ + qB + q0) * D_ + d0) >> 1;
            size_t i1 = ((size_t)(b * LQ_ + qB + q0 + 8) * D_ + d0) >> 1;
            g_T[i0] = h16(acc[mi][nj][0] * rza) | (h16(acc[mi][nj][1] * rza) << 16);
            g_T[i1] = h16(acc[mi][nj][2] * rzb) | (h16(acc[mi][nj][3] * rzb) << 16);
        }
    }
}

// =====================================================================
// k_AB: accQ = E''@Qf (1L), accT = E''@T (1L) in one K sweep (2 MMA terms).
//   Stage = {E 16K | Q 16K | T 16K} = 48K; 3 stages.
// =====================================================================
#define KA_RZ 0
#define KA_BUF 1024
#define KA_STAGE 49152
#define KA_DYN (1024 + 3 * KA_STAGE)

__global__ void __launch_bounds__(512, 1) k_AB(const float* __restrict__ C,
                                               float* __restrict__ out) {
    extern __shared__ char sm[];
    u32 sb = s2u(sm);
    int tid = threadIdx.x, lane = tid & 31, wid = tid >> 5;
    int b = blockIdx.y, cB = blockIdx.x * 128;
    float* rzs = (float*)(sm + KA_RZ);
    if (tid < 128) {
        const float* p = &g_Z1p[((size_t)b * LC_ + cB + tid) * 4];
        rzs[tid] = 1.f / (p[0] + p[1] + p[2] + p[3]);
    }
    const __half* EP = (const __half*)g_E;
    const __half* QP = (const __half*)g_Qf;
    const __half* TP = (const __half*)g_T;
    size_t Eoff = ((size_t)b * LC_ + cB) * LQ_;
    size_t Qoff = (size_t)(b * D_) * LQ_;
    size_t Toff = (size_t)(b * LQ_) * D_;
    const float* Cb = C + (size_t)b * D_ * LC_ + cB;
    float* ob = out + (size_t)b * 4 * D_ * LC_ + cB;
    float* stgQ = (float*)(sm + KA_BUF);
    float* stgT = stgQ + 128 * 132;
    int wm = wid >> 2, wn = wid & 3;
    int m0w = wm * 32, n0w = wn * 32;
    int r = lane >> 2, cp = (lane & 3) * 2;

    #pragma unroll
    for (int pc = 0; pc < 2; pc++) {
        int q0 = pc * 64;
        u32 st = sb + KA_BUF + pc * KA_STAGE;
        cpyN128<512, 1>(st,         EP + Eoff + q0, EP, LQ_, tid);
        cpyN128<512, 1>(st + 16384, QP + Qoff + q0, QP, LQ_, tid);
        cpyT64<512, 1> (st + 32768, TP + Toff + (size_t)q0 * D_, TP, D_, tid);
        CP_COMMIT();
    }

    float accQ[2][4][4] = {}, accT[2][4][4] = {};
    for (int ci = 0; ci < 8; ci++) {
        if (ci < 7) CP_WAIT1(); else CP_WAIT0();
        __syncthreads();
        if (ci < 6) {
            int q0 = (ci + 2) * 64;
            u32 st = sb + KA_BUF + ((ci + 2) % 3) * KA_STAGE;
            cpyN128<512, 1>(st,         EP + Eoff + q0, EP, LQ_, tid);
            cpyN128<512, 1>(st + 16384, QP + Qoff + q0, QP, LQ_, tid);
            cpyT64<512, 1> (st + 32768, TP + Toff + (size_t)q0 * D_, TP, D_, tid);
            CP_COMMIT();
        }
        u32 bb = sb + KA_BUF + (ci % 3) * KA_STAGE;
        mma_chunk_dual(accQ, accT, bb, bb + 16384, bb + 32768, m0w, n0w, lane);
    }
    __syncthreads();

    #pragma unroll
    for (int mi = 0; mi < 2; mi++) {
        int m0 = m0w + mi * 16 + r;
        float rza = rzs[m0], rzb = rzs[m0 + 8];
        #pragma unroll
        for (int nj = 0; nj < 4; nj++) {
            int n0 = n0w + nj * 8 + cp;
            stgQ[n0 * 132 + m0]           = accQ[mi][nj][0] * rza;
            stgQ[(n0 + 1) * 132 + m0]     = accQ[mi][nj][1] * rza;
            stgQ[n0 * 132 + m0 + 8]       = accQ[mi][nj][2] * rzb;
            stgQ[(n0 + 1) * 132 + m0 + 8] = accQ[mi][nj][3] * rzb;
            stgT[n0 * 132 + m0]           = accT[mi][nj][0] * rza;
            stgT[(n0 + 1) * 132 + m0]     = accT[mi][nj][1] * rza;
            stgT[n0 * 132 + m0 + 8]       = accT[mi][nj][2] * rzb;
            stgT[(n0 + 1) * 132 + m0 + 8] = accT[mi][nj][3] * rzb;
        }
    }
    __syncthreads();
    for (int idx = tid; idx < 128 * 128; idx += 512) {
        int dd = idx >> 7, c = idx & 127;
        float a  = stgQ[dd * 132 + c];
        float bm = stgT[dd * 132 + c];
        float cv = Cb[(size_t)dd * LC_ + c];
        ob[(size_t)(128 + dd) * LC_ + c] = a;
        ob[(size_t)(256 + dd) * LC_ + c] = cv * a;
        ob[(size_t)(384 + dd) * LC_ + c] = cv * bm;
    }
}

// =====================================================================
extern "C" void kernel_launch(void* const* d_in, const int* in_sizes, int n_in,
                              void* d_out, int out_size) {
    const float* C     = (const float*)d_in[0];
    const float* Q     = (const float*)d_in[1];
    const int*   Cmask = (const int*)  d_in[2];
    const int*   Qmask = (const int*)  d_in[3];
    const float* w_c   = (const float*)d_in[4];
    const float* w_q   = (const float*)d_in[5];
    const float* w_mul = (const float*)d_in[6];
    const float* bias  = (const float*)d_in[7];
    float* out = (float*)d_out;

    cudaFuncSetAttribute(k_S,  cudaFuncAttributeMaxDynamicSharedMemorySize, KS_DYN);
    cudaFuncSetAttribute(k_T,  cudaFuncAttributeMaxDynamicSharedMemorySize, KT_DYN);
    cudaFuncSetAttribute(k_AB, cudaFuncAttributeMaxDynamicSharedMemorySize, KA_DYN);

    k_cvtC<<<dim3(16, 32), 256>>>(C, Cmask, w_mul, w_c, bias, out);
    k_cvtQ<<<32, 512>>>(Q, w_q);
    k_S<<<dim3(4, 16, 32), 256, KS_DYN>>>(Qmask, Cmask);
    k_T<<<dim3(4, 32), 512, KT_DYN>>>();
    k_AB<<<dim3(16, 32), 512, KA_DYN>>>(C, out);
}